// round 4
// baseline (speedup 1.0000x reference)
#include <cuda_runtime.h>
#include <cuda_fp16.h>
#include <cstdint>

#define T_TOKENS 8192
#define DDIM     1024
#define FDIM     4096
#define NEXP     8
#define CAPC     2048
#define NSLOTS   16384   // E*C == T*K

// ---------------- scratch ----------------------------------------------------
__device__ __align__(256) __half g_W1T[(size_t)NEXP * FDIM * DDIM]; // [E][F][D]
__device__ __align__(256) __half g_W2T[(size_t)NEXP * DDIM * FDIM]; // [E][D][F]
__device__ __align__(256) __half g_H  [(size_t)T_TOKENS * DDIM];
__device__ __align__(256) __half g_X  [(size_t)NSLOTS * DDIM];
__device__ __align__(256) __half g_Mid[(size_t)NSLOTS * FDIM];
__device__ __align__(256) float  g_Y  [(size_t)NSLOTS * DDIM];
__device__ int    g_slot_src[NSLOTS];
__device__ int    g_assign_slot[NSLOTS];
__device__ int    g_epair[T_TOKENS];
__device__ float2 g_gates[T_TOKENS];

// ---------------- helpers ----------------------------------------------------
__device__ __forceinline__ uint32_t smem_u32(const void* p) {
    uint32_t a;
    asm("{ .reg .u64 t; cvta.to.shared.u64 t, %1; cvt.u32.u64 %0, t; }" : "=r"(a) : "l"(p));
    return a;
}
#define SWZ(o) ((o) ^ (((o) >> 3) & 0x70))

__device__ __forceinline__ void cp_async16(uint32_t dst, const void* src) {
    asm volatile("cp.async.cg.shared.global [%0], [%1], 16;" :: "r"(dst), "l"(src));
}
__device__ __forceinline__ void cp_commit() {
    asm volatile("cp.async.commit_group;" ::: "memory");
}
__device__ __forceinline__ void cp_wait1() {
    asm volatile("cp.async.wait_group 1;" ::: "memory");
}
__device__ __forceinline__ void ldsm_x4(uint32_t* r, uint32_t addr) {
    asm volatile("ldmatrix.sync.aligned.m8n8.x4.shared.b16 {%0,%1,%2,%3}, [%4];"
                 : "=r"(r[0]), "=r"(r[1]), "=r"(r[2]), "=r"(r[3]) : "r"(addr));
}
__device__ __forceinline__ void mma16816(float* c, const uint32_t* a, const uint32_t* b) {
    asm volatile(
        "mma.sync.aligned.m16n8k16.row.col.f32.f16.f16.f32 "
        "{%0,%1,%2,%3}, {%4,%5,%6,%7}, {%8,%9}, {%0,%1,%2,%3};"
        : "+f"(c[0]), "+f"(c[1]), "+f"(c[2]), "+f"(c[3])
        : "r"(a[0]), "r"(a[1]), "r"(a[2]), "r"(a[3]), "r"(b[0]), "r"(b[1]));
}

// ---------------- weight transpose + fp16 quantize ---------------------------
__global__ void transpose_w1_kernel(const float* __restrict__ src) {
    __shared__ float tile[32][33];
    const int R = DDIM, Cc = FDIM;
    int e = blockIdx.z, r0 = blockIdx.y * 32, c0 = blockIdx.x * 32;
    int tx = threadIdx.x, ty = threadIdx.y;
    const float* s = src + (size_t)e * R * Cc;
    for (int i = 0; i < 32; i += 8)
        tile[ty + i][tx] = s[(size_t)(r0 + ty + i) * Cc + c0 + tx];
    __syncthreads();
    __half* d = g_W1T + (size_t)e * Cc * R;
    for (int i = 0; i < 32; i += 8)
        d[(size_t)(c0 + ty + i) * R + r0 + tx] = __float2half(tile[tx][ty + i]);
}
__global__ void transpose_w2_kernel(const float* __restrict__ src) {
    __shared__ float tile[32][33];
    const int R = FDIM, Cc = DDIM;
    int e = blockIdx.z, r0 = blockIdx.y * 32, c0 = blockIdx.x * 32;
    int tx = threadIdx.x, ty = threadIdx.y;
    const float* s = src + (size_t)e * R * Cc;
    for (int i = 0; i < 32; i += 8)
        tile[ty + i][tx] = s[(size_t)(r0 + ty + i) * Cc + c0 + tx];
    __syncthreads();
    __half* d = g_W2T + (size_t)e * Cc * R;
    for (int i = 0; i < 32; i += 8)
        d[(size_t)(c0 + ty + i) * R + r0 + tx] = __float2half(tile[tx][ty + i]);
}

// ---------------- RMSNorm + router + top-2 -----------------------------------
__global__ void rms_router_kernel(const float* __restrict__ x,
                                  const float* __restrict__ rw,
                                  const float* __restrict__ wr) {
    const int t = blockIdx.x, tid = threadIdx.x; // 256 threads
    const float4 xv = ((const float4*)(x + (size_t)t * DDIM))[tid];
    float ss = xv.x * xv.x + xv.y * xv.y + xv.z * xv.z + xv.w * xv.w;
    for (int d = 16; d; d >>= 1) ss += __shfl_xor_sync(0xffffffffu, ss, d);
    __shared__ float wred[8];
    if ((tid & 31) == 0) wred[tid >> 5] = ss;
    __syncthreads();
    float tot = 0.f;
#pragma unroll
    for (int i = 0; i < 8; i++) tot += wred[i];
    float scale = 1.0f / sqrtf(tot * (1.0f / DDIM) + 1e-6f);
    const float4 rwv = ((const float4*)rw)[tid];
    float h0 = xv.x * scale * rwv.x, h1 = xv.y * scale * rwv.y;
    float h2 = xv.z * scale * rwv.z, h3 = xv.w * scale * rwv.w;
    __half2* hp = (__half2*)(g_H + (size_t)t * DDIM + tid * 4);
    hp[0] = __floats2half2_rn(h0, h1);
    hp[1] = __floats2half2_rn(h2, h3);
    float lg[8];
#pragma unroll
    for (int e = 0; e < 8; e++) lg[e] = 0.f;
    float hj[4] = {h0, h1, h2, h3};
#pragma unroll
    for (int j = 0; j < 4; j++) {
        const float4* wrow = (const float4*)(wr + (size_t)(tid * 4 + j) * 8);
        float4 wa = wrow[0], wb = wrow[1];
        lg[0] += hj[j] * wa.x; lg[1] += hj[j] * wa.y; lg[2] += hj[j] * wa.z; lg[3] += hj[j] * wa.w;
        lg[4] += hj[j] * wb.x; lg[5] += hj[j] * wb.y; lg[6] += hj[j] * wb.z; lg[7] += hj[j] * wb.w;
    }
    __shared__ float part[8][264];
#pragma unroll
    for (int e = 0; e < 8; e++) part[e][tid] = lg[e];
    __syncthreads();
    __shared__ float logitv[8];
    {
        int w = tid >> 5, l = tid & 31;
        float s = 0.f;
        for (int i = l; i < 256; i += 32) s += part[w][i];
        for (int d = 16; d; d >>= 1) s += __shfl_xor_sync(0xffffffffu, s, d);
        if (l == 0) logitv[w] = s;
    }
    __syncthreads();
    if (tid == 0) {
        float l[8], m = -1e30f;
#pragma unroll
        for (int e = 0; e < 8; e++) { l[e] = logitv[e]; m = fmaxf(m, l[e]); }
        float p[8], s = 0.f;
#pragma unroll
        for (int e = 0; e < 8; e++) { p[e] = expf(l[e] - m); s += p[e]; }
        int i1 = 0;
#pragma unroll
        for (int e = 1; e < 8; e++) if (p[e] > p[i1]) i1 = e;
        int i2 = (i1 == 0) ? 1 : 0;
#pragma unroll
        for (int e = 0; e < 8; e++) if (e != i1 && p[e] > p[i2]) i2 = e;
        g_epair[t] = i1 | (i2 << 8);
        float inv = 1.0f / s;
        g_gates[t] = make_float2(p[i1] * inv, p[i2] * inv);
    }
}

// ---------------- capacity scan (single CTA) ---------------------------------
__global__ void scan_kernel() {
    const int t = threadIdx.x; // 1024 threads, 16 assignments each
    for (int i = t; i < NSLOTS; i += 1024) g_slot_src[i] = -1;
    __syncthreads();
    int cnt[8];
#pragma unroll
    for (int e = 0; e < 8; e++) cnt[e] = 0;
    int eloc[16];
    for (int j = 0; j < 16; j++) {
        int a = t * 16 + j;
        int pair = g_epair[a >> 1];
        int e = (a & 1) ? ((pair >> 8) & 0xFF) : (pair & 0xFF);
        eloc[j] = e;
        cnt[e]++;
    }
    int inc[8];
    unsigned lane = t & 31, warp = t >> 5;
#pragma unroll
    for (int e = 0; e < 8; e++) {
        int v = cnt[e];
        for (int d = 1; d < 32; d <<= 1) {
            int u = __shfl_up_sync(0xffffffffu, v, d);
            if (lane >= d) v += u;
        }
        inc[e] = v;
    }
    __shared__ int wtot[8][32];
    __shared__ int woff[8][32];
    if (lane == 31)
#pragma unroll
        for (int e = 0; e < 8; e++) wtot[e][warp] = inc[e];
    __syncthreads();
    if (warp == 0) {
#pragma unroll
        for (int e = 0; e < 8; e++) {
            int v = wtot[e][lane], orig = v;
            for (int d = 1; d < 32; d <<= 1) {
                int u = __shfl_up_sync(0xffffffffu, v, d);
                if (lane >= d) v += u;
            }
            woff[e][lane] = v - orig;
        }
    }
    __syncthreads();
    int base[8], run[8];
#pragma unroll
    for (int e = 0; e < 8; e++) { base[e] = woff[e][warp] + inc[e] - cnt[e]; run[e] = 0; }
    for (int j = 0; j < 16; j++) {
        int a = t * 16 + j;
        int e = eloc[j];
        int pos = base[e] + run[e]++;
        if (pos < CAPC) {
            int slot = e * CAPC + pos;
            g_assign_slot[a] = slot;
            g_slot_src[slot] = a >> 1;
        } else {
            g_assign_slot[a] = -1;
        }
    }
}

// ---------------- dispatch / combine -----------------------------------------
__global__ void dispatch_kernel() {
    int s = blockIdx.x; // 16384 blocks x 128 threads
    int src = g_slot_src[s];
    uint4* dst = (uint4*)(g_X + (size_t)s * DDIM);
    if (src < 0) {
        dst[threadIdx.x] = make_uint4(0, 0, 0, 0);
    } else {
        const uint4* sp = (const uint4*)(g_H + (size_t)src * DDIM);
        dst[threadIdx.x] = sp[threadIdx.x];
    }
}
__global__ void combine_kernel(float* __restrict__ out) {
    int t = blockIdx.x, i = threadIdx.x; // 8192 x 256
    int a0 = g_assign_slot[2 * t], a1 = g_assign_slot[2 * t + 1];
    float2 g = g_gates[t];
    float4 acc = make_float4(0.f, 0.f, 0.f, 0.f);
    if (a0 >= 0) {
        float4 y = ((const float4*)(g_Y + (size_t)a0 * DDIM))[i];
        acc.x += g.x * y.x; acc.y += g.x * y.y; acc.z += g.x * y.z; acc.w += g.x * y.w;
    }
    if (a1 >= 0) {
        float4 y = ((const float4*)(g_Y + (size_t)a1 * DDIM))[i];
        acc.x += g.y * y.x; acc.y += g.y * y.y; acc.z += g.y * y.z; acc.w += g.y * y.w;
    }
    ((float4*)(out + (size_t)t * DDIM))[i] = acc;
}

// ---------------- HMMA GEMM: CTA 128x128, kc=64, 3-stage cp.async ------------
static constexpr int STAGE_BYTES = 32768;   // A 16KB + B 16KB
static constexpr int NSTAGE = 3;
static constexpr int GEMM_SMEM = NSTAGE * STAGE_BYTES;

template <int PASS>
__global__ void __launch_bounds__(256, 2) moe_gemm_kernel() {
    constexpr int Ktot = (PASS == 0) ? DDIM : FDIM;
    constexpr int Ntot = (PASS == 0) ? FDIM : DDIM;
    constexpr int kIters = Ktot / 64;
    const __half* A = (PASS == 0) ? g_X : g_Mid;
    const __half* B = (PASS == 0) ? g_W1T : g_W2T;

    extern __shared__ char smem[];
    const uint32_t sbase = smem_u32(smem);
    const int m0 = blockIdx.x * 128, n0 = blockIdx.y * 128, e = blockIdx.z;
    const int tid = threadIdx.x, wid = tid >> 5, lane = tid & 31;
    const int mwarp = (wid & 1) * 64, nwarp = (wid >> 1) * 32;

    const __half* Ae = A + (size_t)e * CAPC * Ktot;
    const __half* Be = B + (size_t)e * Ntot * Ktot;

    // cp.async source precompute: 2048 16B chunks, 8 per thread
    const __half* gsrc[8];
    uint32_t sdst[8];
#pragma unroll
    for (int it = 0; it < 8; it++) {
        int c = tid + it * 256;
        if (c < 1024) {
            int row = c >> 3, col = c & 7;
            gsrc[it] = Ae + (size_t)(m0 + row) * Ktot + col * 8;
            sdst[it] = SWZ(row * 128 + col * 16);
        } else {
            int cc = c - 1024;
            int row = cc >> 3, col = cc & 7;
            gsrc[it] = Be + (size_t)(n0 + row) * Ktot + col * 8;
            sdst[it] = 16384 + SWZ(row * 128 + col * 16);
        }
    }

    auto load_stage = [&](int ks, int buf) {
        uint32_t sb = sbase + buf * STAGE_BYTES;
        int kb = ks * 64;
#pragma unroll
        for (int it = 0; it < 8; it++)
            cp_async16(sb + sdst[it], gsrc[it] + kb);
    };

    // ldmatrix per-lane address terms
    const int arow = ((lane >> 3) & 1) * 8 + (lane & 7);
    const int ak16 = ((lane >> 4) & 1) * 16;
    const int brow = ((lane >> 4) & 1) * 8 + (lane & 7);
    const int bk16 = ((lane >> 3) & 1) * 16;
    uint32_t aTerm[4], aMask[4], bTerm[2], bMask[2];
#pragma unroll
    for (int mf = 0; mf < 4; mf++) {
        int r = mwarp + mf * 16 + arow;
        aTerm[mf] = r * 128;
        aMask[mf] = (r & 7) << 4;
    }
#pragma unroll
    for (int np = 0; np < 2; np++) {
        int r = nwarp + np * 16 + brow;
        bTerm[np] = 16384 + r * 128;
        bMask[np] = (r & 7) << 4;
    }

    float acc[4][4][4];
#pragma unroll
    for (int mf = 0; mf < 4; mf++)
#pragma unroll
        for (int nf = 0; nf < 4; nf++)
#pragma unroll
            for (int c = 0; c < 4; c++) acc[mf][nf][c] = 0.f;

    // prologue: prefetch 2 stages
    load_stage(0, 0); cp_commit();
    load_stage(1, 1); cp_commit();

    for (int k = 0; k < kIters; k++) {
        const int buf = k % 3;
        cp_wait1();
        __syncthreads();
        if (k + 2 < kIters) load_stage(k + 2, (k + 2) % 3);
        cp_commit();

        const uint32_t sb = sbase + buf * STAGE_BYTES;
#pragma unroll
        for (int kk = 0; kk < 4; kk++) {
            uint32_t a[4][4], b[4][2];
#pragma unroll
            for (int mf = 0; mf < 4; mf++)
                ldsm_x4(a[mf], sb + aTerm[mf] + (((uint32_t)(kk * 32 + ak16)) ^ aMask[mf]));
#pragma unroll
            for (int np = 0; np < 2; np++) {
                uint32_t r[4];
                ldsm_x4(r, sb + bTerm[np] + (((uint32_t)(kk * 32 + bk16)) ^ bMask[np]));
                b[np * 2][0] = r[0]; b[np * 2][1] = r[1];
                b[np * 2 + 1][0] = r[2]; b[np * 2 + 1][1] = r[3];
            }
#pragma unroll
            for (int mf = 0; mf < 4; mf++)
#pragma unroll
                for (int nf = 0; nf < 4; nf++)
                    mma16816(acc[mf][nf], a[mf], b[nf]);
        }
        __syncthreads();
    }

    // epilogue
    const int rbase = m0 + mwarp + (lane >> 2);
    const int cbase = n0 + nwarp + (lane & 3) * 2;
#pragma unroll
    for (int mf = 0; mf < 4; mf++) {
#pragma unroll
        for (int half_m = 0; half_m < 2; half_m++) {
            const int r = rbase + mf * 16 + half_m * 8;
            const size_t orow = (size_t)(e * CAPC + r);
#pragma unroll
            for (int nf = 0; nf < 4; nf++) {
                float v0 = acc[mf][nf][half_m * 2];
                float v1 = acc[mf][nf][half_m * 2 + 1];
                const int col = cbase + nf * 8;
                if (PASS == 0) {
                    float g0 = 0.5f * v0 * (1.0f + erff(v0 * 0.70710678118654752f));
                    float g1 = 0.5f * v1 * (1.0f + erff(v1 * 0.70710678118654752f));
                    *(__half2*)(g_Mid + orow * FDIM + col) = __floats2half2_rn(g0, g1);
                } else {
                    *(float2*)(g_Y + orow * DDIM + col) = make_float2(v0, v1);
                }
            }
        }
    }
}

// ---------------- launch ------------------------------------------------------
extern "C" void kernel_launch(void* const* d_in, const int* in_sizes, int n_in,
                              void* d_out, int out_size) {
    const float* x    = (const float*)d_in[0];
    const float* rmsw = (const float*)d_in[1];
    const float* wr   = (const float*)d_in[2];
    const float* w1   = (const float*)d_in[3];
    const float* w2   = (const float*)d_in[4];
    float* out = (float*)d_out;

    cudaFuncSetAttribute(moe_gemm_kernel<0>, cudaFuncAttributeMaxDynamicSharedMemorySize, GEMM_SMEM);
    cudaFuncSetAttribute(moe_gemm_kernel<1>, cudaFuncAttributeMaxDynamicSharedMemorySize, GEMM_SMEM);

    transpose_w1_kernel<<<dim3(FDIM / 32, DDIM / 32, NEXP), dim3(32, 8)>>>(w1);
    transpose_w2_kernel<<<dim3(DDIM / 32, FDIM / 32, NEXP), dim3(32, 8)>>>(w2);
    rms_router_kernel<<<T_TOKENS, 256>>>(x, rmsw, wr);
    scan_kernel<<<1, 1024>>>();
    dispatch_kernel<<<NSLOTS, 128>>>();
    moe_gemm_kernel<0><<<dim3(CAPC / 128, FDIM / 128, NEXP), 256, GEMM_SMEM>>>();
    moe_gemm_kernel<1><<<dim3(CAPC / 128, DDIM / 128, NEXP), 256, GEMM_SMEM>>>();
    combine_kernel<<<T_TOKENS, 256>>>(out);
}

// round 5
// speedup vs baseline: 1.0208x; 1.0208x over previous
#include <cuda_runtime.h>
#include <cuda_fp16.h>
#include <cstdint>

#define T_TOKENS 8192
#define DDIM     1024
#define FDIM     4096
#define NEXP     8
#define CAPC     2048
#define NSLOTS   16384   // E*C == T*K

// ---------------- scratch ----------------------------------------------------
__device__ __align__(256) __half g_W1T[(size_t)NEXP * FDIM * DDIM]; // [E][F][D]
__device__ __align__(256) __half g_W2T[(size_t)NEXP * DDIM * FDIM]; // [E][D][F]
__device__ __align__(256) __half g_H  [(size_t)T_TOKENS * DDIM];
__device__ __align__(256) __half g_Mid[(size_t)NSLOTS * FDIM];
__device__ __align__(256) float  g_Y  [(size_t)NSLOTS * DDIM];
__device__ int    g_slot_src[NSLOTS];
__device__ int    g_assign_slot[NSLOTS];
__device__ int    g_epair[T_TOKENS];
__device__ float2 g_gates[T_TOKENS];

// ---------------- helpers ----------------------------------------------------
__device__ __forceinline__ uint32_t smem_u32(const void* p) {
    uint32_t a;
    asm("{ .reg .u64 t; cvta.to.shared.u64 t, %1; cvt.u32.u64 %0, t; }" : "=r"(a) : "l"(p));
    return a;
}
#define SWZ(o) ((o) ^ (((o) >> 3) & 0x70))

__device__ __forceinline__ void cp_async16(uint32_t dst, const void* src) {
    asm volatile("cp.async.cg.shared.global [%0], [%1], 16;" :: "r"(dst), "l"(src));
}
__device__ __forceinline__ void cp_async16z(uint32_t dst, const void* src, uint32_t bytes) {
    asm volatile("cp.async.cg.shared.global [%0], [%1], 16, %2;" :: "r"(dst), "l"(src), "r"(bytes));
}
__device__ __forceinline__ void cp_commit() {
    asm volatile("cp.async.commit_group;" ::: "memory");
}
__device__ __forceinline__ void cp_wait1() {
    asm volatile("cp.async.wait_group 1;" ::: "memory");
}
__device__ __forceinline__ void ldsm_x4(uint32_t* r, uint32_t addr) {
    asm volatile("ldmatrix.sync.aligned.m8n8.x4.shared.b16 {%0,%1,%2,%3}, [%4];"
                 : "=r"(r[0]), "=r"(r[1]), "=r"(r[2]), "=r"(r[3]) : "r"(addr));
}
__device__ __forceinline__ void mma16816(float* c, const uint32_t* a, const uint32_t* b) {
    asm volatile(
        "mma.sync.aligned.m16n8k16.row.col.f32.f16.f16.f32 "
        "{%0,%1,%2,%3}, {%4,%5,%6,%7}, {%8,%9}, {%0,%1,%2,%3};"
        : "+f"(c[0]), "+f"(c[1]), "+f"(c[2]), "+f"(c[3])
        : "r"(a[0]), "r"(a[1]), "r"(a[2]), "r"(a[3]), "r"(b[0]), "r"(b[1]));
}

// ---------------- weight transpose + fp16 quantize ---------------------------
__global__ void transpose_w1_kernel(const float* __restrict__ src) {
    __shared__ float tile[32][33];
    const int R = DDIM, Cc = FDIM;
    int e = blockIdx.z, r0 = blockIdx.y * 32, c0 = blockIdx.x * 32;
    int tx = threadIdx.x, ty = threadIdx.y;
    const float* s = src + (size_t)e * R * Cc;
    for (int i = 0; i < 32; i += 8)
        tile[ty + i][tx] = s[(size_t)(r0 + ty + i) * Cc + c0 + tx];
    __syncthreads();
    __half* d = g_W1T + (size_t)e * Cc * R;
    for (int i = 0; i < 32; i += 8)
        d[(size_t)(c0 + ty + i) * R + r0 + tx] = __float2half(tile[tx][ty + i]);
}
__global__ void transpose_w2_kernel(const float* __restrict__ src) {
    __shared__ float tile[32][33];
    const int R = FDIM, Cc = DDIM;
    int e = blockIdx.z, r0 = blockIdx.y * 32, c0 = blockIdx.x * 32;
    int tx = threadIdx.x, ty = threadIdx.y;
    const float* s = src + (size_t)e * R * Cc;
    for (int i = 0; i < 32; i += 8)
        tile[ty + i][tx] = s[(size_t)(r0 + ty + i) * Cc + c0 + tx];
    __syncthreads();
    __half* d = g_W2T + (size_t)e * Cc * R;
    for (int i = 0; i < 32; i += 8)
        d[(size_t)(c0 + ty + i) * R + r0 + tx] = __float2half(tile[tx][ty + i]);
}

// ---------------- RMSNorm + router + top-2 -----------------------------------
__global__ void rms_router_kernel(const float* __restrict__ x,
                                  const float* __restrict__ rw,
                                  const float* __restrict__ wr) {
    const int t = blockIdx.x, tid = threadIdx.x; // 256 threads
    const float4 xv = ((const float4*)(x + (size_t)t * DDIM))[tid];
    float ss = xv.x * xv.x + xv.y * xv.y + xv.z * xv.z + xv.w * xv.w;
    for (int d = 16; d; d >>= 1) ss += __shfl_xor_sync(0xffffffffu, ss, d);
    __shared__ float wred[8];
    if ((tid & 31) == 0) wred[tid >> 5] = ss;
    __syncthreads();
    float tot = 0.f;
#pragma unroll
    for (int i = 0; i < 8; i++) tot += wred[i];
    float scale = 1.0f / sqrtf(tot * (1.0f / DDIM) + 1e-6f);
    const float4 rwv = ((const float4*)rw)[tid];
    float h0 = xv.x * scale * rwv.x, h1 = xv.y * scale * rwv.y;
    float h2 = xv.z * scale * rwv.z, h3 = xv.w * scale * rwv.w;
    __half2* hp = (__half2*)(g_H + (size_t)t * DDIM + tid * 4);
    hp[0] = __floats2half2_rn(h0, h1);
    hp[1] = __floats2half2_rn(h2, h3);
    float lg[8];
#pragma unroll
    for (int e = 0; e < 8; e++) lg[e] = 0.f;
    float hj[4] = {h0, h1, h2, h3};
#pragma unroll
    for (int j = 0; j < 4; j++) {
        const float4* wrow = (const float4*)(wr + (size_t)(tid * 4 + j) * 8);
        float4 wa = wrow[0], wb = wrow[1];
        lg[0] += hj[j] * wa.x; lg[1] += hj[j] * wa.y; lg[2] += hj[j] * wa.z; lg[3] += hj[j] * wa.w;
        lg[4] += hj[j] * wb.x; lg[5] += hj[j] * wb.y; lg[6] += hj[j] * wb.z; lg[7] += hj[j] * wb.w;
    }
    __shared__ float part[8][264];
#pragma unroll
    for (int e = 0; e < 8; e++) part[e][tid] = lg[e];
    __syncthreads();
    __shared__ float logitv[8];
    {
        int w = tid >> 5, l = tid & 31;
        float s = 0.f;
        for (int i = l; i < 256; i += 32) s += part[w][i];
        for (int d = 16; d; d >>= 1) s += __shfl_xor_sync(0xffffffffu, s, d);
        if (l == 0) logitv[w] = s;
    }
    __syncthreads();
    if (tid == 0) {
        float l[8], m = -1e30f;
#pragma unroll
        for (int e = 0; e < 8; e++) { l[e] = logitv[e]; m = fmaxf(m, l[e]); }
        float p[8], s = 0.f;
#pragma unroll
        for (int e = 0; e < 8; e++) { p[e] = expf(l[e] - m); s += p[e]; }
        int i1 = 0;
#pragma unroll
        for (int e = 1; e < 8; e++) if (p[e] > p[i1]) i1 = e;
        int i2 = (i1 == 0) ? 1 : 0;
#pragma unroll
        for (int e = 0; e < 8; e++) if (e != i1 && p[e] > p[i2]) i2 = e;
        g_epair[t] = i1 | (i2 << 8);
        float inv = 1.0f / s;
        g_gates[t] = make_float2(p[i1] * inv, p[i2] * inv);
    }
}

// ---------------- capacity scan (single CTA, spill-free) ----------------------
__global__ void scan_kernel() {
    const int t = threadIdx.x; // 1024 threads, 16 assignments each
    for (int i = t; i < NSLOTS; i += 1024) g_slot_src[i] = -1;
    __syncthreads();
    int eloc[16];
#pragma unroll
    for (int j = 0; j < 16; j++) {
        int a = t * 16 + j;
        int pair = g_epair[a >> 1];
        eloc[j] = (a & 1) ? ((pair >> 8) & 0xFF) : (pair & 0xFF);
    }
    int cnt[8];
#pragma unroll
    for (int e = 0; e < 8; e++) {
        int c = 0;
#pragma unroll
        for (int j = 0; j < 16; j++) c += (eloc[j] == e) ? 1 : 0;
        cnt[e] = c;
    }
    unsigned lane = t & 31, warp = t >> 5;
    int inc[8];
#pragma unroll
    for (int e = 0; e < 8; e++) {
        int v = cnt[e];
        for (int d = 1; d < 32; d <<= 1) {
            int u = __shfl_up_sync(0xffffffffu, v, d);
            if (lane >= d) v += u;
        }
        inc[e] = v;
    }
    __shared__ int wtot[8][32];
    __shared__ int woff[8][32];
    if (lane == 31)
#pragma unroll
        for (int e = 0; e < 8; e++) wtot[e][warp] = inc[e];
    __syncthreads();
    if (warp == 0) {
#pragma unroll
        for (int e = 0; e < 8; e++) {
            int v = wtot[e][lane], orig = v;
            for (int d = 1; d < 32; d <<= 1) {
                int u = __shfl_up_sync(0xffffffffu, v, d);
                if (lane >= d) v += u;
            }
            woff[e][lane] = v - orig;
        }
    }
    __syncthreads();
    int base[8];
#pragma unroll
    for (int e = 0; e < 8; e++) base[e] = woff[e][warp] + inc[e] - cnt[e];
#pragma unroll
    for (int j = 0; j < 16; j++) {
        int e = eloc[j];
        int p = 0;
#pragma unroll
        for (int ee = 0; ee < 8; ee++) p += (e == ee) ? base[ee] : 0;
#pragma unroll
        for (int jj = 0; jj < j; jj++) p += (eloc[jj] == e) ? 1 : 0;
        int a = t * 16 + j;
        if (p < CAPC) {
            int slot = e * CAPC + p;
            g_assign_slot[a] = slot;
            g_slot_src[slot] = a >> 1;
        } else {
            g_assign_slot[a] = -1;
        }
    }
}

// ---------------- combine -----------------------------------------------------
__global__ void combine_kernel(float* __restrict__ out) {
    int t = blockIdx.x, i = threadIdx.x; // 8192 x 256
    int a0 = g_assign_slot[2 * t], a1 = g_assign_slot[2 * t + 1];
    float2 g = g_gates[t];
    float4 acc = make_float4(0.f, 0.f, 0.f, 0.f);
    if (a0 >= 0) {
        float4 y = ((const float4*)(g_Y + (size_t)a0 * DDIM))[i];
        acc.x += g.x * y.x; acc.y += g.x * y.y; acc.z += g.x * y.z; acc.w += g.x * y.w;
    }
    if (a1 >= 0) {
        float4 y = ((const float4*)(g_Y + (size_t)a1 * DDIM))[i];
        acc.x += g.y * y.x; acc.y += g.y * y.y; acc.z += g.y * y.z; acc.w += g.y * y.w;
    }
    ((float4*)(out + (size_t)t * DDIM))[i] = acc;
}

// ---------------- HMMA GEMM: CTA 128x128, warp 64x64, kc=64, 3-stage ----------
// 128 threads (4 warps in 2x2), 2 CTAs/SM. PASS0 gathers A rows from g_H via
// slot_src (cp.async zero-fill for empty slots) — no dispatch kernel needed.
static constexpr int STAGE_BYTES = 32768;   // A 16KB + B 16KB
static constexpr int GEMM_SMEM = 3 * STAGE_BYTES;

template <int PASS>
__global__ void __launch_bounds__(128, 2) moe_gemm_kernel() {
    constexpr int Ktot = (PASS == 0) ? DDIM : FDIM;
    constexpr int Ntot = (PASS == 0) ? FDIM : DDIM;
    constexpr int kIters = Ktot / 64;
    const __half* B = (PASS == 0) ? g_W1T : g_W2T;

    extern __shared__ char smem[];
    const uint32_t sbase = smem_u32(smem);
    const int m0 = blockIdx.x * 128, n0 = blockIdx.y * 128, e = blockIdx.z;
    const int tid = threadIdx.x, wid = tid >> 5, lane = tid & 31;
    const int mwarp = (wid & 1) * 64, nwarp = (wid >> 1) * 64;

    const __half* Be = B + (size_t)e * Ntot * Ktot;
    const int acol = (tid & 7) * 8;

    // A sources: 8 rows per thread (rows (tid>>3) + i*16)
    const __half* aptr[8];
    uint32_t abytes[8];
#pragma unroll
    for (int i = 0; i < 8; i++) {
        int row = (tid >> 3) + i * 16;
        if (PASS == 0) {
            int src = g_slot_src[e * CAPC + m0 + row];
            aptr[i] = g_H + (size_t)(src < 0 ? 0 : src) * DDIM + acol;
            abytes[i] = (src < 0) ? 0u : 16u;
        } else {
            aptr[i] = g_Mid + (size_t)(e * CAPC + m0 + row) * FDIM + acol;
            abytes[i] = 16u;
        }
    }
    // smem dst: row stride 2048 per i (swizzle invariant under +16 rows)
    const uint32_t sdstA0 = SWZ((tid >> 3) * 128 + (tid & 7) * 16);
    const __half* bbase = Be + (size_t)(n0 + (tid >> 3)) * Ktot + acol;

    auto load_stage = [&](int ks, int buf) {
        const uint32_t sb = sbase + buf * STAGE_BYTES;
        const int kb = ks * 64;
#pragma unroll
        for (int i = 0; i < 8; i++)
            cp_async16z(sb + sdstA0 + i * 2048, aptr[i] + kb, abytes[i]);
#pragma unroll
        for (int i = 0; i < 8; i++)
            cp_async16(sb + 16384 + sdstA0 + i * 2048, bbase + (size_t)i * 16 * Ktot + kb);
    };

    // ldmatrix lane terms
    const int arow = ((lane >> 3) & 1) * 8 + (lane & 7);
    const int ak16 = ((lane >> 4) & 1) * 16;
    const int brow = ((lane >> 4) & 1) * 8 + (lane & 7);
    const int bk16 = ((lane >> 3) & 1) * 16;
    const uint32_t aMask = (uint32_t)(arow & 7) << 4;
    const uint32_t bMask = (uint32_t)(brow & 7) << 4;
    uint32_t aTerm[4], bTerm[4];
#pragma unroll
    for (int mf = 0; mf < 4; mf++) aTerm[mf] = (mwarp + mf * 16 + arow) * 128;
#pragma unroll
    for (int np = 0; np < 4; np++) bTerm[np] = 16384 + (nwarp + np * 16 + brow) * 128;

    float acc[4][8][4];
#pragma unroll
    for (int mf = 0; mf < 4; mf++)
#pragma unroll
        for (int nf = 0; nf < 8; nf++)
#pragma unroll
            for (int c = 0; c < 4; c++) acc[mf][nf][c] = 0.f;

    load_stage(0, 0); cp_commit();
    load_stage(1, 1); cp_commit();

    for (int k = 0; k < kIters; k++) {
        const int buf = k % 3;
        cp_wait1();
        __syncthreads();
        if (k + 2 < kIters) load_stage(k + 2, (k + 2) % 3);
        cp_commit();

        const uint32_t sb = sbase + buf * STAGE_BYTES;
#pragma unroll
        for (int kk = 0; kk < 4; kk++) {
            uint32_t a[4][4], b[8][2];
#pragma unroll
            for (int mf = 0; mf < 4; mf++)
                ldsm_x4(a[mf], sb + aTerm[mf] + (((uint32_t)(kk * 32 + ak16)) ^ aMask));
#pragma unroll
            for (int np = 0; np < 4; np++) {
                uint32_t r[4];
                ldsm_x4(r, sb + bTerm[np] + (((uint32_t)(kk * 32 + bk16)) ^ bMask));
                b[np * 2][0] = r[0]; b[np * 2][1] = r[1];
                b[np * 2 + 1][0] = r[2]; b[np * 2 + 1][1] = r[3];
            }
#pragma unroll
            for (int mf = 0; mf < 4; mf++)
#pragma unroll
                for (int nf = 0; nf < 8; nf++)
                    mma16816(acc[mf][nf], a[mf], b[nf]);
        }
        __syncthreads();
    }

    // epilogue
    const int rbase = m0 + mwarp + (lane >> 2);
    const int cbase = n0 + nwarp + (lane & 3) * 2;
#pragma unroll
    for (int mf = 0; mf < 4; mf++) {
#pragma unroll
        for (int half_m = 0; half_m < 2; half_m++) {
            const int r = rbase + mf * 16 + half_m * 8;
            const size_t orow = (size_t)(e * CAPC + r);
#pragma unroll
            for (int nf = 0; nf < 8; nf++) {
                float v0 = acc[mf][nf][half_m * 2];
                float v1 = acc[mf][nf][half_m * 2 + 1];
                const int col = cbase + nf * 8;
                if (PASS == 0) {
                    float g0 = 0.5f * v0 * (1.0f + erff(v0 * 0.70710678118654752f));
                    float g1 = 0.5f * v1 * (1.0f + erff(v1 * 0.70710678118654752f));
                    *(__half2*)(g_Mid + orow * FDIM + col) = __floats2half2_rn(g0, g1);
                } else {
                    *(float2*)(g_Y + orow * DDIM + col) = make_float2(v0, v1);
                }
            }
        }
    }
}

// ---------------- launch ------------------------------------------------------
extern "C" void kernel_launch(void* const* d_in, const int* in_sizes, int n_in,
                              void* d_out, int out_size) {
    const float* x    = (const float*)d_in[0];
    const float* rmsw = (const float*)d_in[1];
    const float* wr   = (const float*)d_in[2];
    const float* w1   = (const float*)d_in[3];
    const float* w2   = (const float*)d_in[4];
    float* out = (float*)d_out;

    cudaFuncSetAttribute(moe_gemm_kernel<0>, cudaFuncAttributeMaxDynamicSharedMemorySize, GEMM_SMEM);
    cudaFuncSetAttribute(moe_gemm_kernel<1>, cudaFuncAttributeMaxDynamicSharedMemorySize, GEMM_SMEM);

    rms_router_kernel<<<T_TOKENS, 256>>>(x, rmsw, wr);
    scan_kernel<<<1, 1024>>>();
    transpose_w1_kernel<<<dim3(FDIM / 32, DDIM / 32, NEXP), dim3(32, 8)>>>(w1);
    moe_gemm_kernel<0><<<dim3(CAPC / 128, FDIM / 128, NEXP), 128, GEMM_SMEM>>>();
    transpose_w2_kernel<<<dim3(DDIM / 32, FDIM / 32, NEXP), dim3(32, 8)>>>(w2);
    moe_gemm_kernel<1><<<dim3(CAPC / 128, DDIM / 128, NEXP), 128, GEMM_SMEM>>>();
    combine_kernel<<<T_TOKENS, 256>>>(out);
}

// round 6
// speedup vs baseline: 1.0419x; 1.0206x over previous
#include <cuda_runtime.h>
#include <cuda_fp16.h>
#include <cstdint>

#define T_TOKENS 8192
#define DDIM     1024
#define FDIM     4096
#define NEXP     8
#define CAPC     2048
#define NSLOTS   16384   // E*C == T*K

// ---------------- scratch ----------------------------------------------------
__device__ __align__(256) __half g_W1T[(size_t)NEXP * FDIM * DDIM]; // [E][F][D]
__device__ __align__(256) __half g_W2T[(size_t)NEXP * DDIM * FDIM]; // [E][D][F]
__device__ __align__(256) __half g_H  [(size_t)T_TOKENS * DDIM];
__device__ __align__(256) __half g_Mid[(size_t)NSLOTS * FDIM];
__device__ __align__(256) float  g_Y  [(size_t)NSLOTS * DDIM];
__device__ int    g_slot_src[NSLOTS];
__device__ int    g_assign_slot[NSLOTS];
__device__ int    g_epair[T_TOKENS];
__device__ float2 g_gates[T_TOKENS];

// ---------------- helpers ----------------------------------------------------
__device__ __forceinline__ uint32_t smem_u32(const void* p) {
    uint32_t a;
    asm("{ .reg .u64 t; cvta.to.shared.u64 t, %1; cvt.u32.u64 %0, t; }" : "=r"(a) : "l"(p));
    return a;
}
#define SWZ(o) ((o) ^ (((o) >> 3) & 0x70))

__device__ __forceinline__ void cp_async16(uint32_t dst, const void* src) {
    asm volatile("cp.async.cg.shared.global [%0], [%1], 16;" :: "r"(dst), "l"(src));
}
__device__ __forceinline__ void cp_async16z(uint32_t dst, const void* src, uint32_t bytes) {
    asm volatile("cp.async.cg.shared.global [%0], [%1], 16, %2;" :: "r"(dst), "l"(src), "r"(bytes));
}
__device__ __forceinline__ void cp_commit() {
    asm volatile("cp.async.commit_group;" ::: "memory");
}
__device__ __forceinline__ void cp_wait1() {
    asm volatile("cp.async.wait_group 1;" ::: "memory");
}
__device__ __forceinline__ void ldsm_x4(uint32_t* r, uint32_t addr) {
    asm volatile("ldmatrix.sync.aligned.m8n8.x4.shared.b16 {%0,%1,%2,%3}, [%4];"
                 : "=r"(r[0]), "=r"(r[1]), "=r"(r[2]), "=r"(r[3]) : "r"(addr));
}
__device__ __forceinline__ void mma16816(float* c, const uint32_t* a, const uint32_t* b) {
    asm volatile(
        "mma.sync.aligned.m16n8k16.row.col.f32.f16.f16.f32 "
        "{%0,%1,%2,%3}, {%4,%5,%6,%7}, {%8,%9}, {%0,%1,%2,%3};"
        : "+f"(c[0]), "+f"(c[1]), "+f"(c[2]), "+f"(c[3])
        : "r"(a[0]), "r"(a[1]), "r"(a[2]), "r"(a[3]), "r"(b[0]), "r"(b[1]));
}

// ---------------- weight transpose + fp16 quantize ---------------------------
__global__ void transpose_w1_kernel(const float* __restrict__ src) {
    __shared__ float tile[32][33];
    const int R = DDIM, Cc = FDIM;
    int e = blockIdx.z, r0 = blockIdx.y * 32, c0 = blockIdx.x * 32;
    int tx = threadIdx.x, ty = threadIdx.y;
    const float* s = src + (size_t)e * R * Cc;
    for (int i = 0; i < 32; i += 8)
        tile[ty + i][tx] = s[(size_t)(r0 + ty + i) * Cc + c0 + tx];
    __syncthreads();
    __half* d = g_W1T + (size_t)e * Cc * R;
    for (int i = 0; i < 32; i += 8)
        d[(size_t)(c0 + ty + i) * R + r0 + tx] = __float2half(tile[tx][ty + i]);
}
__global__ void transpose_w2_kernel(const float* __restrict__ src) {
    __shared__ float tile[32][33];
    const int R = FDIM, Cc = DDIM;
    int e = blockIdx.z, r0 = blockIdx.y * 32, c0 = blockIdx.x * 32;
    int tx = threadIdx.x, ty = threadIdx.y;
    const float* s = src + (size_t)e * R * Cc;
    for (int i = 0; i < 32; i += 8)
        tile[ty + i][tx] = s[(size_t)(r0 + ty + i) * Cc + c0 + tx];
    __syncthreads();
    __half* d = g_W2T + (size_t)e * Cc * R;
    for (int i = 0; i < 32; i += 8)
        d[(size_t)(c0 + ty + i) * R + r0 + tx] = __float2half(tile[tx][ty + i]);
}

// ---------------- RMSNorm + router + top-2 -----------------------------------
__global__ void rms_router_kernel(const float* __restrict__ x,
                                  const float* __restrict__ rw,
                                  const float* __restrict__ wr) {
    const int t = blockIdx.x, tid = threadIdx.x; // 256 threads
    const float4 xv = ((const float4*)(x + (size_t)t * DDIM))[tid];
    float ss = xv.x * xv.x + xv.y * xv.y + xv.z * xv.z + xv.w * xv.w;
    for (int d = 16; d; d >>= 1) ss += __shfl_xor_sync(0xffffffffu, ss, d);
    __shared__ float wred[8];
    if ((tid & 31) == 0) wred[tid >> 5] = ss;
    __syncthreads();
    float tot = 0.f;
#pragma unroll
    for (int i = 0; i < 8; i++) tot += wred[i];
    float scale = 1.0f / sqrtf(tot * (1.0f / DDIM) + 1e-6f);
    const float4 rwv = ((const float4*)rw)[tid];
    float h0 = xv.x * scale * rwv.x, h1 = xv.y * scale * rwv.y;
    float h2 = xv.z * scale * rwv.z, h3 = xv.w * scale * rwv.w;
    __half2* hp = (__half2*)(g_H + (size_t)t * DDIM + tid * 4);
    hp[0] = __floats2half2_rn(h0, h1);
    hp[1] = __floats2half2_rn(h2, h3);
    float lg[8];
#pragma unroll
    for (int e = 0; e < 8; e++) lg[e] = 0.f;
    float hj[4] = {h0, h1, h2, h3};
#pragma unroll
    for (int j = 0; j < 4; j++) {
        const float4* wrow = (const float4*)(wr + (size_t)(tid * 4 + j) * 8);
        float4 wa = wrow[0], wb = wrow[1];
        lg[0] += hj[j] * wa.x; lg[1] += hj[j] * wa.y; lg[2] += hj[j] * wa.z; lg[3] += hj[j] * wa.w;
        lg[4] += hj[j] * wb.x; lg[5] += hj[j] * wb.y; lg[6] += hj[j] * wb.z; lg[7] += hj[j] * wb.w;
    }
    __shared__ float part[8][264];
#pragma unroll
    for (int e = 0; e < 8; e++) part[e][tid] = lg[e];
    __syncthreads();
    __shared__ float logitv[8];
    {
        int w = tid >> 5, l = tid & 31;
        float s = 0.f;
        for (int i = l; i < 256; i += 32) s += part[w][i];
        for (int d = 16; d; d >>= 1) s += __shfl_xor_sync(0xffffffffu, s, d);
        if (l == 0) logitv[w] = s;
    }
    __syncthreads();
    if (tid == 0) {
        float l[8], m = -1e30f;
#pragma unroll
        for (int e = 0; e < 8; e++) { l[e] = logitv[e]; m = fmaxf(m, l[e]); }
        float p[8], s = 0.f;
#pragma unroll
        for (int e = 0; e < 8; e++) { p[e] = expf(l[e] - m); s += p[e]; }
        int i1 = 0;
#pragma unroll
        for (int e = 1; e < 8; e++) if (p[e] > p[i1]) i1 = e;
        int i2 = (i1 == 0) ? 1 : 0;
#pragma unroll
        for (int e = 0; e < 8; e++) if (e != i1 && p[e] > p[i2]) i2 = e;
        g_epair[t] = i1 | (i2 << 8);
        float inv = 1.0f / s;
        g_gates[t] = make_float2(p[i1] * inv, p[i2] * inv);
    }
}

// ---------------- capacity scan (single CTA, spill-free) ----------------------
__global__ void scan_kernel() {
    const int t = threadIdx.x; // 1024 threads, 16 assignments each
    for (int i = t; i < NSLOTS; i += 1024) g_slot_src[i] = -1;
    __syncthreads();
    int eloc[16];
#pragma unroll
    for (int j = 0; j < 16; j++) {
        int a = t * 16 + j;
        int pair = g_epair[a >> 1];
        eloc[j] = (a & 1) ? ((pair >> 8) & 0xFF) : (pair & 0xFF);
    }
    int cnt[8];
#pragma unroll
    for (int e = 0; e < 8; e++) {
        int c = 0;
#pragma unroll
        for (int j = 0; j < 16; j++) c += (eloc[j] == e) ? 1 : 0;
        cnt[e] = c;
    }
    unsigned lane = t & 31, warp = t >> 5;
    int inc[8];
#pragma unroll
    for (int e = 0; e < 8; e++) {
        int v = cnt[e];
        for (int d = 1; d < 32; d <<= 1) {
            int u = __shfl_up_sync(0xffffffffu, v, d);
            if (lane >= d) v += u;
        }
        inc[e] = v;
    }
    __shared__ int wtot[8][32];
    __shared__ int woff[8][32];
    if (lane == 31)
#pragma unroll
        for (int e = 0; e < 8; e++) wtot[e][warp] = inc[e];
    __syncthreads();
    if (warp == 0) {
#pragma unroll
        for (int e = 0; e < 8; e++) {
            int v = wtot[e][lane], orig = v;
            for (int d = 1; d < 32; d <<= 1) {
                int u = __shfl_up_sync(0xffffffffu, v, d);
                if (lane >= d) v += u;
            }
            woff[e][lane] = v - orig;
        }
    }
    __syncthreads();
    int base[8];
#pragma unroll
    for (int e = 0; e < 8; e++) base[e] = woff[e][warp] + inc[e] - cnt[e];
#pragma unroll
    for (int j = 0; j < 16; j++) {
        int e = eloc[j];
        int p = 0;
#pragma unroll
        for (int ee = 0; ee < 8; ee++) p += (e == ee) ? base[ee] : 0;
#pragma unroll
        for (int jj = 0; jj < j; jj++) p += (eloc[jj] == e) ? 1 : 0;
        int a = t * 16 + j;
        if (p < CAPC) {
            int slot = e * CAPC + p;
            g_assign_slot[a] = slot;
            g_slot_src[slot] = a >> 1;
        } else {
            g_assign_slot[a] = -1;
        }
    }
}

// ---------------- combine -----------------------------------------------------
__global__ void combine_kernel(float* __restrict__ out) {
    int t = blockIdx.x, i = threadIdx.x; // 8192 x 256
    int a0 = g_assign_slot[2 * t], a1 = g_assign_slot[2 * t + 1];
    float2 g = g_gates[t];
    float4 acc = make_float4(0.f, 0.f, 0.f, 0.f);
    if (a0 >= 0) {
        float4 y = ((const float4*)(g_Y + (size_t)a0 * DDIM))[i];
        acc.x += g.x * y.x; acc.y += g.x * y.y; acc.z += g.x * y.z; acc.w += g.x * y.w;
    }
    if (a1 >= 0) {
        float4 y = ((const float4*)(g_Y + (size_t)a1 * DDIM))[i];
        acc.x += g.y * y.x; acc.y += g.y * y.y; acc.z += g.y * y.z; acc.w += g.y * y.w;
    }
    ((float4*)(out + (size_t)t * DDIM))[i] = acc;
}

// ---------------- HMMA GEMM: CTA 128x128, warp 64x64, kc=64, 3-stage ----------
// 128 threads (4 warps in 2x2), 2 CTAs/SM. kk-loop software-pipelined with
// double-buffered ldmatrix fragments so mma chains cover ldsm latency.
static constexpr int STAGE_BYTES = 32768;   // A 16KB + B 16KB
static constexpr int GEMM_SMEM = 3 * STAGE_BYTES;

template <int PASS>
__global__ void __launch_bounds__(128, 2) moe_gemm_kernel() {
    constexpr int Ktot = (PASS == 0) ? DDIM : FDIM;
    constexpr int Ntot = (PASS == 0) ? FDIM : DDIM;
    constexpr int kIters = Ktot / 64;
    const __half* B = (PASS == 0) ? g_W1T : g_W2T;

    extern __shared__ char smem[];
    const uint32_t sbase = smem_u32(smem);
    const int m0 = blockIdx.x * 128, n0 = blockIdx.y * 128, e = blockIdx.z;
    const int tid = threadIdx.x, wid = tid >> 5, lane = tid & 31;
    const int mwarp = (wid & 1) * 64, nwarp = (wid >> 1) * 64;

    const __half* Be = B + (size_t)e * Ntot * Ktot;
    const int acol = (tid & 7) * 8;

    // A sources: 8 rows per thread (rows (tid>>3) + i*16)
    const __half* aptr[8];
    uint32_t abytes[8];
#pragma unroll
    for (int i = 0; i < 8; i++) {
        int row = (tid >> 3) + i * 16;
        if (PASS == 0) {
            int src = g_slot_src[e * CAPC + m0 + row];
            aptr[i] = g_H + (size_t)(src < 0 ? 0 : src) * DDIM + acol;
            abytes[i] = (src < 0) ? 0u : 16u;
        } else {
            aptr[i] = g_Mid + (size_t)(e * CAPC + m0 + row) * FDIM + acol;
            abytes[i] = 16u;
        }
    }
    const uint32_t sdstA0 = SWZ((tid >> 3) * 128 + (tid & 7) * 16);
    const __half* bbase = Be + (size_t)(n0 + (tid >> 3)) * Ktot + acol;

    auto load_stage = [&](int ks, int buf) {
        const uint32_t sb = sbase + buf * STAGE_BYTES;
        const int kb = ks * 64;
#pragma unroll
        for (int i = 0; i < 8; i++)
            cp_async16z(sb + sdstA0 + i * 2048, aptr[i] + kb, abytes[i]);
#pragma unroll
        for (int i = 0; i < 8; i++)
            cp_async16(sb + 16384 + sdstA0 + i * 2048, bbase + (size_t)i * 16 * Ktot + kb);
    };

    // ldmatrix lane terms
    const int arow = ((lane >> 3) & 1) * 8 + (lane & 7);
    const int ak16 = ((lane >> 4) & 1) * 16;
    const int brow = ((lane >> 4) & 1) * 8 + (lane & 7);
    const int bk16 = ((lane >> 3) & 1) * 16;
    const uint32_t aMask = (uint32_t)(arow & 7) << 4;
    const uint32_t bMask = (uint32_t)(brow & 7) << 4;
    uint32_t aTerm[4], bTerm[4];
#pragma unroll
    for (int mf = 0; mf < 4; mf++) aTerm[mf] = (mwarp + mf * 16 + arow) * 128;
#pragma unroll
    for (int np = 0; np < 4; np++) bTerm[np] = 16384 + (nwarp + np * 16 + brow) * 128;

    float acc[4][8][4];
#pragma unroll
    for (int mf = 0; mf < 4; mf++)
#pragma unroll
        for (int nf = 0; nf < 8; nf++)
#pragma unroll
            for (int c = 0; c < 4; c++) acc[mf][nf][c] = 0.f;

    // double-buffered fragments
    uint32_t afr[2][4][4], bfr[2][8][2];

    auto frag_load = [&](int kk, int pb, uint32_t sb) {
#pragma unroll
        for (int mf = 0; mf < 4; mf++)
            ldsm_x4(afr[pb][mf], sb + aTerm[mf] + (((uint32_t)(kk * 32 + ak16)) ^ aMask));
#pragma unroll
        for (int np = 0; np < 4; np++) {
            uint32_t r[4];
            ldsm_x4(r, sb + bTerm[np] + (((uint32_t)(kk * 32 + bk16)) ^ bMask));
            bfr[pb][np * 2][0] = r[0]; bfr[pb][np * 2][1] = r[1];
            bfr[pb][np * 2 + 1][0] = r[2]; bfr[pb][np * 2 + 1][1] = r[3];
        }
    };

    load_stage(0, 0); cp_commit();
    load_stage(1, 1); cp_commit();

    for (int k = 0; k < kIters; k++) {
        const int buf = k % 3;
        cp_wait1();
        __syncthreads();
        const uint32_t sb = sbase + buf * STAGE_BYTES;
        frag_load(0, 0, sb);                    // prime slice 0 (overlaps next cp.async issue)
        if (k + 2 < kIters) load_stage(k + 2, (k + 2) % 3);
        cp_commit();

#pragma unroll
        for (int kk = 0; kk < 4; kk++) {
            const int pb = kk & 1;
            if (kk < 3) frag_load(kk + 1, pb ^ 1, sb);   // prefetch next slice
#pragma unroll
            for (int mf = 0; mf < 4; mf++)
#pragma unroll
                for (int nf = 0; nf < 8; nf++)
                    mma16816(acc[mf][nf], afr[pb][mf], bfr[pb][nf]);
        }
        __syncthreads();
    }

    // epilogue
    const int rbase = m0 + mwarp + (lane >> 2);
    const int cbase = n0 + nwarp + (lane & 3) * 2;
#pragma unroll
    for (int mf = 0; mf < 4; mf++) {
#pragma unroll
        for (int half_m = 0; half_m < 2; half_m++) {
            const int r = rbase + mf * 16 + half_m * 8;
            const size_t orow = (size_t)(e * CAPC + r);
#pragma unroll
            for (int nf = 0; nf < 8; nf++) {
                float v0 = acc[mf][nf][half_m * 2];
                float v1 = acc[mf][nf][half_m * 2 + 1];
                const int col = cbase + nf * 8;
                if (PASS == 0) {
                    float g0 = 0.5f * v0 * (1.0f + erff(v0 * 0.70710678118654752f));
                    float g1 = 0.5f * v1 * (1.0f + erff(v1 * 0.70710678118654752f));
                    *(__half2*)(g_Mid + orow * FDIM + col) = __floats2half2_rn(g0, g1);
                } else {
                    *(float2*)(g_Y + orow * DDIM + col) = make_float2(v0, v1);
                }
            }
        }
    }
}

// ---------------- launch ------------------------------------------------------
extern "C" void kernel_launch(void* const* d_in, const int* in_sizes, int n_in,
                              void* d_out, int out_size) {
    const float* x    = (const float*)d_in[0];
    const float* rmsw = (const float*)d_in[1];
    const float* wr   = (const float*)d_in[2];
    const float* w1   = (const float*)d_in[3];
    const float* w2   = (const float*)d_in[4];
    float* out = (float*)d_out;

    cudaFuncSetAttribute(moe_gemm_kernel<0>, cudaFuncAttributeMaxDynamicSharedMemorySize, GEMM_SMEM);
    cudaFuncSetAttribute(moe_gemm_kernel<1>, cudaFuncAttributeMaxDynamicSharedMemorySize, GEMM_SMEM);

    rms_router_kernel<<<T_TOKENS, 256>>>(x, rmsw, wr);
    scan_kernel<<<1, 1024>>>();
    transpose_w1_kernel<<<dim3(FDIM / 32, DDIM / 32, NEXP), dim3(32, 8)>>>(w1);
    moe_gemm_kernel<0><<<dim3(CAPC / 128, FDIM / 128, NEXP), 128, GEMM_SMEM>>>();
    transpose_w2_kernel<<<dim3(DDIM / 32, FDIM / 32, NEXP), dim3(32, 8)>>>(w2);
    moe_gemm_kernel<1><<<dim3(CAPC / 128, DDIM / 128, NEXP), 128, GEMM_SMEM>>>();
    combine_kernel<<<T_TOKENS, 256>>>(out);
}